// round 1
// baseline (speedup 1.0000x reference)
#include <cuda_runtime.h>
#include <cstdint>

// ----------------------------------------------------------------------------
// Problem constants
// ----------------------------------------------------------------------------
#define BATCH 4
#define SEQ   2048
#define DMODEL 1024
#define NHEAD 16
#define HDIM  64
#define N_QKV 3072
#define QK_SCALE 0.125f   // 1/sqrt(64)

// ----------------------------------------------------------------------------
// Device scratch (allocation-free rule: __device__ globals)
// ----------------------------------------------------------------------------
__device__ alignas(128) float g_Q[BATCH * NHEAD * SEQ * HDIM];
__device__ alignas(128) float g_K[BATCH * NHEAD * SEQ * HDIM];
__device__ alignas(128) float g_V[BATCH * NHEAD * SEQ * HDIM];
__device__ alignas(128) float g_O[BATCH * SEQ * DMODEL];
__device__ alignas(128) float g_cos[SEQ * (HDIM / 2)];
__device__ alignas(128) float g_sin[SEQ * (HDIM / 2)];

// ----------------------------------------------------------------------------
// Kernel 0: RoPE cos/sin table  (theta_i = 10000^(-2i/64), ang = pos * theta_i)
// ----------------------------------------------------------------------------
__global__ void rope_table_kernel() {
    int idx = blockIdx.x * blockDim.x + threadIdx.x;   // SEQ * 32 = 65536
    int pos = idx >> 5;
    int i   = idx & 31;
    float inv_freq = powf(10000.0f, (-2.0f * (float)i) / 64.0f);
    float ang = (float)pos * inv_freq;
    float s, c;
    sincosf(ang, &s, &c);
    g_cos[idx] = c;
    g_sin[idx] = s;
}

// ----------------------------------------------------------------------------
// Tiled fp32 GEMM: C[m,n] = sum_k A[m,k] * W[n,k]
//   BM=128, BN=64, BK=16, 256 threads, 8x4 micro-tile.
// EPI==1: QKV epilogue (split into Q/K/V, apply RoPE to Q/K, re-layout [B,H,S,hd])
// EPI==0: plain epilogue to Cout (out projection), A source = g_O
// ----------------------------------------------------------------------------
#define GBM 128
#define GBN 64
#define GBK 16

template <int EPI>
__global__ __launch_bounds__(256) void gemm_kernel(const float* __restrict__ Ain,
                                                   const float* __restrict__ W,
                                                   float* __restrict__ Cout) {
    constexpr int Kdim = DMODEL;
    __shared__ float As[GBK][GBM];
    __shared__ float Bs[GBK][GBN];

    const float* A = (EPI == 0) ? (const float*)g_O : Ain;

    int tid = threadIdx.x;
    int tx = tid & 15;          // 16 col-groups of 4
    int ty = tid >> 4;          // 16 row-groups of 8
    int bm = blockIdx.y * GBM;
    int bn = blockIdx.x * GBN;

    float acc[8][4];
#pragma unroll
    for (int i = 0; i < 8; i++)
#pragma unroll
        for (int j = 0; j < 4; j++) acc[i][j] = 0.0f;

    for (int k0 = 0; k0 < Kdim; k0 += GBK) {
        // Load A tile: 128x16 = 512 float4
#pragma unroll
        for (int it = 0; it < 2; it++) {
            int f = tid + it * 256;
            int r = f >> 2;
            int c = (f & 3) << 2;
            float4 v = *(const float4*)&A[(size_t)(bm + r) * Kdim + k0 + c];
            As[c + 0][r] = v.x;
            As[c + 1][r] = v.y;
            As[c + 2][r] = v.z;
            As[c + 3][r] = v.w;
        }
        // Load W tile: 64x16 = 256 float4
        {
            int r = tid >> 2;
            int c = (tid & 3) << 2;
            float4 v = *(const float4*)&W[(size_t)(bn + r) * Kdim + k0 + c];
            Bs[c + 0][r] = v.x;
            Bs[c + 1][r] = v.y;
            Bs[c + 2][r] = v.z;
            Bs[c + 3][r] = v.w;
        }
        __syncthreads();

#pragma unroll
        for (int kk = 0; kk < GBK; kk++) {
            float a[8], b[4];
            *(float4*)&a[0] = *(const float4*)&As[kk][ty * 8];
            *(float4*)&a[4] = *(const float4*)&As[kk][ty * 8 + 4];
            *(float4*)&b[0] = *(const float4*)&Bs[kk][tx * 4];
#pragma unroll
            for (int i = 0; i < 8; i++)
#pragma unroll
                for (int j = 0; j < 4; j++) acc[i][j] += a[i] * b[j];
        }
        __syncthreads();
    }

    if (EPI == 0) {
        // Plain store to Cout [8192, 1024]
#pragma unroll
        for (int i = 0; i < 8; i++) {
            int m = bm + ty * 8 + i;
            float4 v = make_float4(acc[i][0], acc[i][1], acc[i][2], acc[i][3]);
            *(float4*)&Cout[(size_t)m * DMODEL + bn + tx * 4] = v;
        }
    } else {
        // QKV epilogue. BN=64 aligns exactly to one head of one section.
        int sect = bn >> 10;              // 0:q, 1:k, 2:v
        int h = (bn & 1023) >> 6;         // head index
        float* dst = (sect == 0) ? g_Q : ((sect == 1) ? g_K : g_V);
#pragma unroll
        for (int i = 0; i < 8; i++) {
            int m = bm + ty * 8 + i;
            int b = m >> 11;
            int s = m & (SEQ - 1);
            size_t base = ((size_t)((b * NHEAD + h) * SEQ + s)) * HDIM;
            if (sect == 2) {
                float4 v = make_float4(acc[i][0], acc[i][1], acc[i][2], acc[i][3]);
                *(float4*)&dst[base + tx * 4] = v;
            } else {
                // columns tx*4 .. tx*4+3 = two RoPE pairs, freq indices 2*tx, 2*tx+1
                int fi = tx * 2;
                float c0 = g_cos[s * 32 + fi],     s0 = g_sin[s * 32 + fi];
                float c1 = g_cos[s * 32 + fi + 1], s1 = g_sin[s * 32 + fi + 1];
                float r0 = acc[i][0] * c0 - acc[i][1] * s0;
                float r1 = acc[i][0] * s0 + acc[i][1] * c0;
                float r2 = acc[i][2] * c1 - acc[i][3] * s1;
                float r3 = acc[i][2] * s1 + acc[i][3] * c1;
                *(float4*)&dst[base + tx * 4] = make_float4(r0, r1, r2, r3);
            }
        }
    }
}

// ----------------------------------------------------------------------------
// Kernel 2: fp32 causal flash attention.
//  Block = 256 threads = 8 warps. Each warp owns 4 query rows (BQ=32).
//  Key tiles of 64. Online softmax. Output written to g_O as [B, S, H*hd].
// ----------------------------------------------------------------------------
__global__ __launch_bounds__(256) void flash_kernel(const int* __restrict__ pm) {
    __shared__ float Qs[32][64];       // pre-scaled by QK_SCALE
    __shared__ float Ks[64][68];       // pad 68: conflict-free float4 reads
    __shared__ float Vs[64][64];
    __shared__ float Ps[8][4][64];     // per-warp softmax weights
    __shared__ int   pmS[64];

    int tid = threadIdx.x;
    int w = tid >> 5;
    int lane = tid & 31;
    int bh = blockIdx.y;               // b*16 + h
    int b = bh >> 4;
    int h = bh & 15;
    int qb = blockIdx.x * 32;

    const float* Qg = g_Q + (size_t)bh * SEQ * HDIM;
    const float* Kg = g_K + (size_t)bh * SEQ * HDIM;
    const float* Vg = g_V + (size_t)bh * SEQ * HDIM;

    // Load Q block (32x64), pre-scaled
#pragma unroll
    for (int it = 0; it < 2; it++) {
        int f = tid + it * 256;
        int r = f >> 4;
        int c = (f & 15) << 2;
        float4 v = *(const float4*)&Qg[(size_t)(qb + r) * HDIM + c];
        v.x *= QK_SCALE; v.y *= QK_SCALE; v.z *= QK_SCALE; v.w *= QK_SCALE;
        *(float4*)&Qs[r][c] = v;
    }

    float m_r[4], l_r[4], acc[4][2];
#pragma unroll
    for (int r = 0; r < 4; r++) {
        m_r[r] = -1e30f;
        l_r[r] = 0.0f;
        acc[r][0] = 0.0f;
        acc[r][1] = 0.0f;
    }

    int nt = (qb + 32 + 63) >> 6;      // number of 64-key tiles (causal)

    for (int t = 0; t < nt; t++) {
        int kt = t * 64;
        __syncthreads();               // previous tile compute done before overwrite
        // Load K, V tiles (each 64x64 = 1024 float4)
#pragma unroll
        for (int it = 0; it < 4; it++) {
            int f = tid + it * 256;
            int kk = f >> 4;
            int c = (f & 15) << 2;
            *(float4*)&Ks[kk][c] = *(const float4*)&Kg[(size_t)(kt + kk) * HDIM + c];
            *(float4*)&Vs[kk][c] = *(const float4*)&Vg[(size_t)(kt + kk) * HDIM + c];
        }
        if (tid < 64) pmS[tid] = pm[b * SEQ + kt + tid];
        __syncthreads();

        // ---- Scores: each lane handles keys (lane, lane+32) for 4 rows ----
        float sacc[4][2];
#pragma unroll
        for (int r = 0; r < 4; r++) { sacc[r][0] = 0.0f; sacc[r][1] = 0.0f; }

#pragma unroll
        for (int d4 = 0; d4 < 16; d4++) {
            float4 k0 = *(const float4*)&Ks[lane][d4 * 4];
            float4 k1 = *(const float4*)&Ks[lane + 32][d4 * 4];
#pragma unroll
            for (int r = 0; r < 4; r++) {
                float4 q = *(const float4*)&Qs[w * 4 + r][d4 * 4];
                sacc[r][0] += q.x * k0.x + q.y * k0.y + q.z * k0.z + q.w * k0.w;
                sacc[r][1] += q.x * k1.x + q.y * k1.y + q.z * k1.z + q.w * k1.w;
            }
        }

        int kg0 = kt + lane;
        int kg1 = kt + lane + 32;
        bool p0ok = (pmS[lane] != 0);
        bool p1ok = (pmS[lane + 32] != 0);

#pragma unroll
        for (int r = 0; r < 4; r++) {
            int qi = qb + w * 4 + r;
            float s0 = (p0ok && kg0 <= qi) ? sacc[r][0] : -1e30f;
            float s1 = (p1ok && kg1 <= qi) ? sacc[r][1] : -1e30f;
            float tmax = fmaxf(s0, s1);
#pragma unroll
            for (int o = 16; o > 0; o >>= 1)
                tmax = fmaxf(tmax, __shfl_xor_sync(0xFFFFFFFFu, tmax, o));
            float mn = fmaxf(m_r[r], tmax);
            float alpha = __expf(m_r[r] - mn);
            float p0 = (s0 > -1e29f) ? __expf(s0 - mn) : 0.0f;
            float p1 = (s1 > -1e29f) ? __expf(s1 - mn) : 0.0f;
            float ps = p0 + p1;
#pragma unroll
            for (int o = 16; o > 0; o >>= 1)
                ps += __shfl_xor_sync(0xFFFFFFFFu, ps, o);
            l_r[r] = l_r[r] * alpha + ps;
            m_r[r] = mn;
            acc[r][0] *= alpha;
            acc[r][1] *= alpha;
            Ps[w][r][lane] = p0;
            Ps[w][r][lane + 32] = p1;
        }
        __syncwarp();

        // ---- PV: each lane owns output dims (lane, lane+32) ----
#pragma unroll
        for (int k4 = 0; k4 < 16; k4++) {
            float pr[4][4];
#pragma unroll
            for (int r = 0; r < 4; r++)
                *(float4*)pr[r] = *(const float4*)&Ps[w][r][k4 * 4];
#pragma unroll
            for (int o = 0; o < 4; o++) {
                int kk = k4 * 4 + o;
                float v0 = Vs[kk][lane];
                float v1 = Vs[kk][lane + 32];
#pragma unroll
                for (int r = 0; r < 4; r++) {
                    acc[r][0] += pr[r][o] * v0;
                    acc[r][1] += pr[r][o] * v1;
                }
            }
        }
    }

    // Epilogue: O[b, qi, h*64 + d]
#pragma unroll
    for (int r = 0; r < 4; r++) {
        int qi = qb + w * 4 + r;
        float inv = 1.0f / l_r[r];
        size_t base = ((size_t)(b * SEQ + qi)) * DMODEL + h * HDIM;
        g_O[base + lane] = acc[r][0] * inv;
        g_O[base + lane + 32] = acc[r][1] * inv;
    }
}

// ----------------------------------------------------------------------------
// Launch
// ----------------------------------------------------------------------------
extern "C" void kernel_launch(void* const* d_in, const int* in_sizes, int n_in,
                              void* d_out, int out_size) {
    const float* x     = (const float*)d_in[0];
    const int*   pmask = (const int*)d_in[1];
    const float* w_qkv = (const float*)d_in[2];
    const float* w_o   = (const float*)d_in[3];
    float* out = (float*)d_out;

    // 0) RoPE table
    rope_table_kernel<<<SEQ * 32 / 256, 256>>>();

    // 1) QKV projection + RoPE + head re-layout
    gemm_kernel<1><<<dim3(N_QKV / GBN, (BATCH * SEQ) / GBM), 256>>>(x, w_qkv, nullptr);

    // 2) causal flash attention -> g_O [B, S, D]
    flash_kernel<<<dim3(SEQ / 32, BATCH * NHEAD), 256>>>(pmask);

    // 3) output projection: out = g_O @ w_o^T
    gemm_kernel<0><<<dim3(DMODEL / GBN, (BATCH * SEQ) / GBM), 256>>>(nullptr, w_o, out);
}

// round 2
// speedup vs baseline: 3.1578x; 3.1578x over previous
#include <cuda_runtime.h>
#include <cstdint>

// ----------------------------------------------------------------------------
// Problem constants
// ----------------------------------------------------------------------------
#define BATCH 4
#define SEQ   2048
#define DMODEL 1024
#define NHEAD 16
#define HDIM  64
#define N_QKV 3072
#define QK_SCALE 0.125f   // 1/sqrt(64)

// ----------------------------------------------------------------------------
// Device scratch (allocation-free rule: __device__ globals)
// ----------------------------------------------------------------------------
__device__ alignas(128) float g_Q[BATCH * NHEAD * SEQ * HDIM];
__device__ alignas(128) float g_K[BATCH * NHEAD * SEQ * HDIM];
__device__ alignas(128) float g_V[BATCH * NHEAD * SEQ * HDIM];
__device__ alignas(128) float g_O[BATCH * SEQ * DMODEL];
__device__ alignas(128) float g_X[BATCH * SEQ * DMODEL];
__device__ alignas(128) float g_Wqkv[N_QKV * DMODEL];
__device__ alignas(128) float g_Wo[DMODEL * DMODEL];
__device__ alignas(128) float g_cos[SEQ * (HDIM / 2)];
__device__ alignas(128) float g_sin[SEQ * (HDIM / 2)];

// ----------------------------------------------------------------------------
// Helpers: tf32 rounding (rna: unbiased), mma.sync tf32, cp.async
// ----------------------------------------------------------------------------
__device__ __forceinline__ uint32_t f2tf(float x) {
    uint32_t r;
    asm("cvt.rna.tf32.f32 %0, %1;" : "=r"(r) : "f"(x));
    return r;
}
__device__ __forceinline__ float f2tff(float x) { return __uint_as_float(f2tf(x)); }

__device__ __forceinline__ void mma_tf32(float* c,
                                         uint32_t a0, uint32_t a1, uint32_t a2, uint32_t a3,
                                         uint32_t b0, uint32_t b1) {
    asm volatile(
        "mma.sync.aligned.m16n8k8.row.col.f32.tf32.tf32.f32 "
        "{%0,%1,%2,%3},{%4,%5,%6,%7},{%8,%9},{%0,%1,%2,%3};"
        : "+f"(c[0]), "+f"(c[1]), "+f"(c[2]), "+f"(c[3])
        : "r"(a0), "r"(a1), "r"(a2), "r"(a3), "r"(b0), "r"(b1));
}

__device__ __forceinline__ void cp_async16(void* s, const void* g) {
    uint32_t sa = (uint32_t)__cvta_generic_to_shared(s);
    asm volatile("cp.async.cg.shared.global [%0],[%1],16;" :: "r"(sa), "l"(g));
}
#define CP_COMMIT() asm volatile("cp.async.commit_group;")
#define CP_WAIT0()  asm volatile("cp.async.wait_group 0;")
#define CP_WAIT1()  asm volatile("cp.async.wait_group 1;")

// ----------------------------------------------------------------------------
// Kernel: elementwise tf32 rounding prepass (x, w_qkv, w_o)
// ----------------------------------------------------------------------------
__global__ void round_tf32_kernel(const float* __restrict__ in, int which, int n4) {
    int i = blockIdx.x * blockDim.x + threadIdx.x;
    if (i >= n4) return;
    float4 v = ((const float4*)in)[i];
    v.x = f2tff(v.x); v.y = f2tff(v.y); v.z = f2tff(v.z); v.w = f2tff(v.w);
    float* out = (which == 0) ? g_X : ((which == 1) ? g_Wqkv : g_Wo);
    ((float4*)out)[i] = v;
}

// ----------------------------------------------------------------------------
// Kernel: RoPE cos/sin table
// ----------------------------------------------------------------------------
__global__ void rope_table_kernel() {
    int idx = blockIdx.x * blockDim.x + threadIdx.x;   // SEQ * 32
    int pos = idx >> 5;
    int i   = idx & 31;
    float inv_freq = powf(10000.0f, (-2.0f * (float)i) / 64.0f);
    float ang = (float)pos * inv_freq;
    float s, c;
    sincosf(ang, &s, &c);
    g_cos[idx] = c;
    g_sin[idx] = s;
}

// ----------------------------------------------------------------------------
// tf32 tensor-core GEMM: C[m,n] = sum_k A[m,k] * W[n,k]
//  BM=128, BN=128, BK=16, 256 threads = 8 warps (2x4), warp tile 64x32.
//  cp.async double-buffered. Padded smem stride 20 -> conflict-free frags.
//  EPI==1: A=g_X, W=g_Wqkv, epilogue = QKV split + RoPE + [B,H,S,hd] layout
//  EPI==0: A=g_O, W=g_Wo,  epilogue = plain store to Cout
// ----------------------------------------------------------------------------
#define GBM 128
#define GBN 128
#define GBK 16
#define GPAD 20

template <int EPI>
__global__ __launch_bounds__(256) void gemm_mma(float* __restrict__ Cout) {
    __shared__ float As[2][GBM][GPAD];
    __shared__ float Bs[2][GBN][GPAD];

    const float* A = EPI ? (const float*)g_X : (const float*)g_O;
    const float* W = EPI ? (const float*)g_Wqkv : (const float*)g_Wo;
    const int Kd = DMODEL;

    int tid = threadIdx.x;
    int warp = tid >> 5, lane = tid & 31;
    int g = lane >> 2, t = lane & 3;
    int wm = warp >> 2, wn = warp & 3;
    int bm = blockIdx.y * GBM, bn = blockIdx.x * GBN;

    float acc[4][4][4];
#pragma unroll
    for (int i = 0; i < 4; i++)
#pragma unroll
        for (int j = 0; j < 4; j++)
#pragma unroll
            for (int q = 0; q < 4; q++) acc[i][j][q] = 0.0f;

    // Prologue: prefetch 2 stages
#pragma unroll
    for (int s = 0; s < 2; s++) {
        int k0 = s * GBK;
#pragma unroll
        for (int i = 0; i < 2; i++) {
            int f = tid + i * 256;
            int r = f >> 2, c = (f & 3) << 2;
            cp_async16(&As[s][r][c], &A[(size_t)(bm + r) * Kd + k0 + c]);
        }
#pragma unroll
        for (int i = 0; i < 2; i++) {
            int f = tid + i * 256;
            int r = f >> 2, c = (f & 3) << 2;
            cp_async16(&Bs[s][r][c], &W[(size_t)(bn + r) * Kd + k0 + c]);
        }
        CP_COMMIT();
    }

    const int NIT = Kd / GBK;   // 64
    for (int it = 0; it < NIT; it++) {
        if (it + 2 < NIT) { CP_WAIT1(); } else { CP_WAIT0(); }
        __syncthreads();
        int buf = it & 1;
#pragma unroll
        for (int ks = 0; ks < 2; ks++) {
            uint32_t af[4][4], bf[4][2];
#pragma unroll
            for (int mt = 0; mt < 4; mt++) {
                int r = wm * 64 + mt * 16 + g;
                int c = ks * 8 + t;
                af[mt][0] = __float_as_uint(As[buf][r][c]);
                af[mt][1] = __float_as_uint(As[buf][r + 8][c]);
                af[mt][2] = __float_as_uint(As[buf][r][c + 4]);
                af[mt][3] = __float_as_uint(As[buf][r + 8][c + 4]);
            }
#pragma unroll
            for (int nt = 0; nt < 4; nt++) {
                int rr = wn * 32 + nt * 8 + g;
                int c = ks * 8 + t;
                bf[nt][0] = __float_as_uint(Bs[buf][rr][c]);
                bf[nt][1] = __float_as_uint(Bs[buf][rr][c + 4]);
            }
#pragma unroll
            for (int mt = 0; mt < 4; mt++)
#pragma unroll
                for (int nt = 0; nt < 4; nt++)
                    mma_tf32(acc[mt][nt], af[mt][0], af[mt][1], af[mt][2], af[mt][3],
                             bf[nt][0], bf[nt][1]);
        }
        __syncthreads();
        if (it + 2 < NIT) {
            int k0 = (it + 2) * GBK;
#pragma unroll
            for (int i = 0; i < 2; i++) {
                int f = tid + i * 256;
                int r = f >> 2, c = (f & 3) << 2;
                cp_async16(&As[buf][r][c], &A[(size_t)(bm + r) * Kd + k0 + c]);
            }
#pragma unroll
            for (int i = 0; i < 2; i++) {
                int f = tid + i * 256;
                int r = f >> 2, c = (f & 3) << 2;
                cp_async16(&Bs[buf][r][c], &W[(size_t)(bn + r) * Kd + k0 + c]);
            }
            CP_COMMIT();
        }
    }

    if (EPI == 0) {
#pragma unroll
        for (int mt = 0; mt < 4; mt++) {
#pragma unroll
            for (int nt = 0; nt < 4; nt++) {
                int n = bn + wn * 32 + nt * 8 + 2 * t;
                int r = bm + wm * 64 + mt * 16 + g;
                *(float2*)&Cout[(size_t)r * DMODEL + n] =
                    make_float2(acc[mt][nt][0], acc[mt][nt][1]);
                *(float2*)&Cout[(size_t)(r + 8) * DMODEL + n] =
                    make_float2(acc[mt][nt][2], acc[mt][nt][3]);
            }
        }
    } else {
        int sect = bn >> 10;   // 0:q 1:k 2:v (constant per block; 128 | 1024)
        float* dst = (sect == 0) ? g_Q : ((sect == 1) ? g_K : g_V);
#pragma unroll
        for (int mt = 0; mt < 4; mt++) {
#pragma unroll
            for (int nt = 0; nt < 4; nt++) {
                int n = bn + wn * 32 + nt * 8 + 2 * t;
                int hh = (n & 1023) >> 6;
                int d = n & 63;                 // even
                int fi = d >> 1;
                int r0 = bm + wm * 64 + mt * 16 + g;
#pragma unroll
                for (int half = 0; half < 2; half++) {
                    int rr = r0 + half * 8;
                    float v0 = acc[mt][nt][half * 2 + 0];
                    float v1 = acc[mt][nt][half * 2 + 1];
                    int bb = rr >> 11, s = rr & (SEQ - 1);
                    size_t base = ((size_t)((bb * NHEAD + hh) * SEQ + s)) * HDIM + d;
                    float o0, o1;
                    if (sect == 2) { o0 = v0; o1 = v1; }
                    else {
                        float cs = g_cos[s * 32 + fi], sn = g_sin[s * 32 + fi];
                        o0 = v0 * cs - v1 * sn;
                        o1 = v0 * sn + v1 * cs;
                    }
                    *(float2*)&dst[base] = make_float2(f2tff(o0), f2tff(o1));
                }
            }
        }
    }
}

// ----------------------------------------------------------------------------
// Flash attention, tf32 tensor cores.
//  128 threads = 4 warps; BQ=64 (16 rows/warp); key tiles of 64.
//  Dynamic smem: Qs[64][68], Ks[64][68], Vs[64][72], Ps[64][68], pm[64].
//  All fragment-load patterns bank-conflict-free by stride choice.
// ----------------------------------------------------------------------------
#define FQ_STR 68
#define FV_STR 72
#define FLASH_SMEM_BYTES ((64*68 + 64*68 + 64*72 + 64*68) * 4 + 256)

__global__ __launch_bounds__(128) void flash_mma(const int* __restrict__ pm) {
    extern __shared__ char smraw[];
    float (*Qs)[FQ_STR] = (float(*)[FQ_STR])smraw;
    float (*Ks)[FQ_STR] = (float(*)[FQ_STR])(smraw + 64 * FQ_STR * 4);
    float (*Vs)[FV_STR] = (float(*)[FV_STR])(smraw + 2 * 64 * FQ_STR * 4);
    float (*Ps)[FQ_STR] = (float(*)[FQ_STR])(smraw + 2 * 64 * FQ_STR * 4 + 64 * FV_STR * 4);
    int* pmS = (int*)(smraw + 3 * 64 * FQ_STR * 4 + 64 * FV_STR * 4);

    int tid = threadIdx.x;
    int w = tid >> 5, lane = tid & 31;
    int g = lane >> 2, t = lane & 3;
    int bh = blockIdx.y, b = bh >> 4, h = bh & 15;
    int qb = blockIdx.x * 64;

    const float* Qg = g_Q + (size_t)bh * SEQ * HDIM;
    const float* Kg = g_K + (size_t)bh * SEQ * HDIM;
    const float* Vg = g_V + (size_t)bh * SEQ * HDIM;

    // Load Q 64x64, pre-scaled (power-of-2 scale keeps tf32 exact)
#pragma unroll
    for (int i = 0; i < 8; i++) {
        int f = tid + i * 128;
        int r = f >> 4, c = (f & 15) << 2;
        float4 v = *(const float4*)&Qg[(size_t)(qb + r) * HDIM + c];
        v.x *= QK_SCALE; v.y *= QK_SCALE; v.z *= QK_SCALE; v.w *= QK_SCALE;
        *(float4*)&Qs[r][c] = v;
    }

    float m0 = -1e30f, m1 = -1e30f, l0 = 0.0f, l1 = 0.0f;
    float acc[8][4];
#pragma unroll
    for (int i = 0; i < 8; i++)
#pragma unroll
        for (int j = 0; j < 4; j++) acc[i][j] = 0.0f;

    int r0 = qb + w * 16 + g;
    int r1 = r0 + 8;
    int ntile = (qb >> 6) + 1;

    for (int kti = 0; kti < ntile; kti++) {
        int kt = kti * 64;
        __syncthreads();
#pragma unroll
        for (int i = 0; i < 8; i++) {
            int f = tid + i * 128;
            int r = f >> 4, c = (f & 15) << 2;
            *(float4*)&Ks[r][c] = *(const float4*)&Kg[(size_t)(kt + r) * HDIM + c];
            *(float4*)&Vs[r][c] = *(const float4*)&Vg[(size_t)(kt + r) * HDIM + c];
        }
        if (tid < 64) pmS[tid] = pm[b * SEQ + kt + tid];
        __syncthreads();

        // ---- S = Q @ K^T (warp rows 16, cols 64) ----
        float sf[8][4];
#pragma unroll
        for (int i = 0; i < 8; i++)
#pragma unroll
            for (int j = 0; j < 4; j++) sf[i][j] = 0.0f;

#pragma unroll
        for (int kd = 0; kd < 8; kd++) {
            uint32_t a0 = __float_as_uint(Qs[w * 16 + g][kd * 8 + t]);
            uint32_t a1 = __float_as_uint(Qs[w * 16 + g + 8][kd * 8 + t]);
            uint32_t a2 = __float_as_uint(Qs[w * 16 + g][kd * 8 + t + 4]);
            uint32_t a3 = __float_as_uint(Qs[w * 16 + g + 8][kd * 8 + t + 4]);
#pragma unroll
            for (int nk = 0; nk < 8; nk++) {
                uint32_t b0 = __float_as_uint(Ks[nk * 8 + g][kd * 8 + t]);
                uint32_t b1 = __float_as_uint(Ks[nk * 8 + g][kd * 8 + t + 4]);
                mma_tf32(sf[nk], a0, a1, a2, a3, b0, b1);
            }
        }

        // ---- mask + online softmax on C-fragments ----
        float tmax0 = -1e30f, tmax1 = -1e30f;
#pragma unroll
        for (int nk = 0; nk < 8; nk++) {
            int c0 = kt + nk * 8 + 2 * t;
            int c1 = c0 + 1;
            bool k0ok = pmS[nk * 8 + 2 * t] != 0;
            bool k1ok = pmS[nk * 8 + 2 * t + 1] != 0;
            sf[nk][0] = (k0ok && c0 <= r0) ? sf[nk][0] : -1e30f;
            sf[nk][1] = (k1ok && c1 <= r0) ? sf[nk][1] : -1e30f;
            sf[nk][2] = (k0ok && c0 <= r1) ? sf[nk][2] : -1e30f;
            sf[nk][3] = (k1ok && c1 <= r1) ? sf[nk][3] : -1e30f;
            tmax0 = fmaxf(tmax0, fmaxf(sf[nk][0], sf[nk][1]));
            tmax1 = fmaxf(tmax1, fmaxf(sf[nk][2], sf[nk][3]));
        }
        tmax0 = fmaxf(tmax0, __shfl_xor_sync(0xFFFFFFFFu, tmax0, 1));
        tmax0 = fmaxf(tmax0, __shfl_xor_sync(0xFFFFFFFFu, tmax0, 2));
        tmax1 = fmaxf(tmax1, __shfl_xor_sync(0xFFFFFFFFu, tmax1, 1));
        tmax1 = fmaxf(tmax1, __shfl_xor_sync(0xFFFFFFFFu, tmax1, 2));

        float mn0 = fmaxf(m0, tmax0), mn1 = fmaxf(m1, tmax1);
        float al0 = __expf(m0 - mn0), al1 = __expf(m1 - mn1);
        m0 = mn0; m1 = mn1;

        float ps0 = 0.0f, ps1 = 0.0f;
#pragma unroll
        for (int nk = 0; nk < 8; nk++) {
            float p00 = (sf[nk][0] > -1e29f) ? __expf(sf[nk][0] - mn0) : 0.0f;
            float p01 = (sf[nk][1] > -1e29f) ? __expf(sf[nk][1] - mn0) : 0.0f;
            float p10 = (sf[nk][2] > -1e29f) ? __expf(sf[nk][2] - mn1) : 0.0f;
            float p11 = (sf[nk][3] > -1e29f) ? __expf(sf[nk][3] - mn1) : 0.0f;
            ps0 += p00 + p01;
            ps1 += p10 + p11;
            *(float2*)&Ps[w * 16 + g][nk * 8 + 2 * t] =
                make_float2(f2tff(p00), f2tff(p01));
            *(float2*)&Ps[w * 16 + g + 8][nk * 8 + 2 * t] =
                make_float2(f2tff(p10), f2tff(p11));
        }
        ps0 += __shfl_xor_sync(0xFFFFFFFFu, ps0, 1);
        ps0 += __shfl_xor_sync(0xFFFFFFFFu, ps0, 2);
        ps1 += __shfl_xor_sync(0xFFFFFFFFu, ps1, 1);
        ps1 += __shfl_xor_sync(0xFFFFFFFFu, ps1, 2);
        l0 = l0 * al0 + ps0;
        l1 = l1 * al1 + ps1;
#pragma unroll
        for (int nd = 0; nd < 8; nd++) {
            acc[nd][0] *= al0; acc[nd][1] *= al0;
            acc[nd][2] *= al1; acc[nd][3] *= al1;
        }
        __syncwarp();

        // ---- acc += P @ V ----
#pragma unroll
        for (int kk = 0; kk < 8; kk++) {
            uint32_t a0 = __float_as_uint(Ps[w * 16 + g][kk * 8 + t]);
            uint32_t a1 = __float_as_uint(Ps[w * 16 + g + 8][kk * 8 + t]);
            uint32_t a2 = __float_as_uint(Ps[w * 16 + g][kk * 8 + t + 4]);
            uint32_t a3 = __float_as_uint(Ps[w * 16 + g + 8][kk * 8 + t + 4]);
#pragma unroll
            for (int nd = 0; nd < 8; nd++) {
                uint32_t b0 = __float_as_uint(Vs[kk * 8 + t][nd * 8 + g]);
                uint32_t b1 = __float_as_uint(Vs[kk * 8 + t + 4][nd * 8 + g]);
                mma_tf32(acc[nd], a0, a1, a2, a3, b0, b1);
            }
        }
    }

    // Epilogue: O[b, row, h*64+d], tf32-rounded (feeds next tf32 GEMM)
    float inv0 = 1.0f / l0, inv1 = 1.0f / l1;
    size_t base0 = ((size_t)(b * SEQ + r0)) * DMODEL + h * HDIM;
    size_t base1 = ((size_t)(b * SEQ + r1)) * DMODEL + h * HDIM;
#pragma unroll
    for (int nd = 0; nd < 8; nd++) {
        int c = nd * 8 + 2 * t;
        *(float2*)&g_O[base0 + c] =
            make_float2(f2tff(acc[nd][0] * inv0), f2tff(acc[nd][1] * inv0));
        *(float2*)&g_O[base1 + c] =
            make_float2(f2tff(acc[nd][2] * inv1), f2tff(acc[nd][3] * inv1));
    }
}

// ----------------------------------------------------------------------------
// Launch
// ----------------------------------------------------------------------------
extern "C" void kernel_launch(void* const* d_in, const int* in_sizes, int n_in,
                              void* d_out, int out_size) {
    const float* x     = (const float*)d_in[0];
    const int*   pmask = (const int*)d_in[1];
    const float* w_qkv = (const float*)d_in[2];
    const float* w_o   = (const float*)d_in[3];
    float* out = (float*)d_out;

    cudaFuncSetAttribute(flash_mma, cudaFuncAttributeMaxDynamicSharedMemorySize,
                         FLASH_SMEM_BYTES);

    // tf32 rounding prepass (unbiased rna — kills truncation bias)
    round_tf32_kernel<<<(BATCH * SEQ * DMODEL / 4 + 255) / 256, 256>>>(x, 0, BATCH * SEQ * DMODEL / 4);
    round_tf32_kernel<<<(N_QKV * DMODEL / 4 + 255) / 256, 256>>>(w_qkv, 1, N_QKV * DMODEL / 4);
    round_tf32_kernel<<<(DMODEL * DMODEL / 4 + 255) / 256, 256>>>(w_o, 2, DMODEL * DMODEL / 4);

    // RoPE table
    rope_table_kernel<<<SEQ * 32 / 256, 256>>>();

    // QKV projection + RoPE + head layout (tensor cores)
    gemm_mma<1><<<dim3(N_QKV / GBN, (BATCH * SEQ) / GBM), 256>>>(nullptr);

    // Causal flash attention (tensor cores)
    flash_mma<<<dim3(SEQ / 64, BATCH * NHEAD), 128, FLASH_SMEM_BYTES>>>(pmask);

    // Output projection (tensor cores)
    gemm_mma<0><<<dim3(DMODEL / GBN, (BATCH * SEQ) / GBM), 256>>>(out);
}